// round 1
// baseline (speedup 1.0000x reference)
#include <cuda_runtime.h>
#include <cuda_bf16.h>

#define N_NODES 100000
#define N_EDGES 6400000
#define F_IN 5
#define F_HID 5
#define F_OUT 10

// Scratch (allocation-free rule: __device__ globals).
// Rows padded to 8 floats (32B) => one aligned L2 sector per gather,
// and 16B/8B alignment for red.v4/red.v2.
__device__ float g_xpad[N_NODES][8];
__device__ float g_agg1[N_NODES][8];   // [0..4] = segment sum, [5] = degree
__device__ float g_h[N_NODES][8];      // layer-1 output (padded)
__device__ float g_agg2[N_NODES][8];   // [0..4] = segment sum (deg reused from g_agg1)

__device__ __forceinline__ void red_add_v4(float* p, float a, float b, float c, float d) {
    unsigned long long gp = __cvta_generic_to_global((void*)p);
    asm volatile("red.global.add.v4.f32 [%0], {%1,%2,%3,%4};"
                 :: "l"(gp), "f"(a), "f"(b), "f"(c), "f"(d) : "memory");
}
__device__ __forceinline__ void red_add_v2(float* p, float a, float b) {
    unsigned long long gp = __cvta_generic_to_global((void*)p);
    asm volatile("red.global.add.v2.f32 [%0], {%1,%2};"
                 :: "l"(gp), "f"(a), "f"(b) : "memory");
}
__device__ __forceinline__ void red_add_f32(float* p, float a) {
    unsigned long long gp = __cvta_generic_to_global((void*)p);
    asm volatile("red.global.add.f32 [%0], %1;"
                 :: "l"(gp), "f"(a) : "memory");
}

__device__ __forceinline__ float sigmoidf(float z) {
    return 1.0f / (1.0f + __expf(-z));
}

// ---------------------------------------------------------------------------
// K0: pad x into g_xpad and zero both aggregation buffers.
__global__ void k_init(const float* __restrict__ x) {
    int i = blockIdx.x * blockDim.x + threadIdx.x;
    if (i >= N_NODES) return;
    const float* xr = x + i * F_IN;
    float v0 = xr[0], v1 = xr[1], v2 = xr[2], v3 = xr[3], v4 = xr[4];
    *(float4*)&g_xpad[i][0] = make_float4(v0, v1, v2, v3);
    *(float4*)&g_xpad[i][4] = make_float4(v4, 0.f, 0.f, 0.f);
    float4 z = make_float4(0.f, 0.f, 0.f, 0.f);
    *(float4*)&g_agg1[i][0] = z;
    *(float4*)&g_agg1[i][4] = z;
    *(float4*)&g_agg2[i][0] = z;
    *(float4*)&g_agg2[i][4] = z;
}

// ---------------------------------------------------------------------------
// K1: layer-1 edge scatter. 2 atomic messages per edge (v4 + v2[feat4, deg]).
__global__ void k_edge1(const int* __restrict__ src, const int* __restrict__ dst) {
    int e = blockIdx.x * blockDim.x + threadIdx.x;
    if (e >= N_EDGES) return;
    int s = src[e];
    int d = dst[e];
    float4 a  = *(const float4*)&g_xpad[s][0];
    float  a4 = g_xpad[s][4];
    float* p = &g_agg1[d][0];
    red_add_v4(p, a.x, a.y, a.z, a.w);
    red_add_v2(p + 4, a4, 1.0f);   // feature 4 + degree count, one message
}

// ---------------------------------------------------------------------------
// K2: layer-1 node update: h = sigmoid(x@Ws1 + (agg/deg)@Wn1 + b1)
__global__ void k_node1(const float* __restrict__ Ws, const float* __restrict__ Wn,
                        const float* __restrict__ b) {
    int i = blockIdx.x * blockDim.x + threadIdx.x;
    if (i >= N_NODES) return;
    float4 xa = *(const float4*)&g_xpad[i][0];
    float  x4 = g_xpad[i][4];
    float4 ag = *(const float4*)&g_agg1[i][0];
    float4 ag2 = *(const float4*)&g_agg1[i][4];   // .x = feat4 sum, .y = deg
    float inv = 1.0f / fmaxf(ag2.y, 1.0f);
    float xv[5] = {xa.x, xa.y, xa.z, xa.w, x4};
    float hn[5] = {ag.x * inv, ag.y * inv, ag.z * inv, ag.w * inv, ag2.x * inv};
    float o[F_HID];
#pragma unroll
    for (int j = 0; j < F_HID; j++) o[j] = b[j];
#pragma unroll
    for (int k = 0; k < F_IN; k++) {
        float xk = xv[k], hk = hn[k];
#pragma unroll
        for (int j = 0; j < F_HID; j++)
            o[j] += xk * __ldg(&Ws[k * F_HID + j]) + hk * __ldg(&Wn[k * F_HID + j]);
    }
#pragma unroll
    for (int j = 0; j < F_HID; j++) o[j] = sigmoidf(o[j]);
    *(float4*)&g_h[i][0] = make_float4(o[0], o[1], o[2], o[3]);
    *(float4*)&g_h[i][4] = make_float4(o[4], 0.f, 0.f, 0.f);
}

// ---------------------------------------------------------------------------
// K3: layer-2 edge scatter on h. Degree already known -> v4 + scalar red.
__global__ void k_edge2(const int* __restrict__ src, const int* __restrict__ dst) {
    int e = blockIdx.x * blockDim.x + threadIdx.x;
    if (e >= N_EDGES) return;
    int s = src[e];
    int d = dst[e];
    float4 a  = *(const float4*)&g_h[s][0];
    float  a4 = g_h[s][4];
    float* p = &g_agg2[d][0];
    red_add_v4(p, a.x, a.y, a.z, a.w);
    red_add_f32(p + 4, a4);
}

// ---------------------------------------------------------------------------
// K4: layer-2 node update -> out = sigmoid(h@Ws2 + (agg2/deg)@Wn2 + b2)
__global__ void k_node2(const float* __restrict__ Ws, const float* __restrict__ Wn,
                        const float* __restrict__ b, float* __restrict__ out) {
    int i = blockIdx.x * blockDim.x + threadIdx.x;
    if (i >= N_NODES) return;
    float4 ha = *(const float4*)&g_h[i][0];
    float  h4 = g_h[i][4];
    float4 ag = *(const float4*)&g_agg2[i][0];
    float  a4 = g_agg2[i][4];
    float  deg = g_agg1[i][5];
    float inv = 1.0f / fmaxf(deg, 1.0f);
    float hv[5] = {ha.x, ha.y, ha.z, ha.w, h4};
    float hn[5] = {ag.x * inv, ag.y * inv, ag.z * inv, ag.w * inv, a4 * inv};
    float o[F_OUT];
#pragma unroll
    for (int j = 0; j < F_OUT; j++) o[j] = b[j];
#pragma unroll
    for (int k = 0; k < F_HID; k++) {
        float hk = hv[k], nk = hn[k];
#pragma unroll
        for (int j = 0; j < F_OUT; j++)
            o[j] += hk * __ldg(&Ws[k * F_OUT + j]) + nk * __ldg(&Wn[k * F_OUT + j]);
    }
    float* orow = out + i * F_OUT;
#pragma unroll
    for (int j = 0; j < F_OUT; j++) orow[j] = sigmoidf(o[j]);
}

// ---------------------------------------------------------------------------
extern "C" void kernel_launch(void* const* d_in, const int* in_sizes, int n_in,
                              void* d_out, int out_size) {
    const float* x       = (const float*)d_in[0];
    const int*   src     = (const int*)d_in[1];
    const int*   dst     = (const int*)d_in[2];
    const float* W_self1 = (const float*)d_in[3];
    const float* W_neigh1= (const float*)d_in[4];
    const float* b1      = (const float*)d_in[5];
    const float* W_self2 = (const float*)d_in[6];
    const float* W_neigh2= (const float*)d_in[7];
    const float* b2      = (const float*)d_in[8];
    float* out = (float*)d_out;

    const int TB = 256;
    int nb_nodes = (N_NODES + TB - 1) / TB;
    int nb_edges = (N_EDGES + TB - 1) / TB;

    k_init<<<nb_nodes, TB>>>(x);
    k_edge1<<<nb_edges, TB>>>(src, dst);
    k_node1<<<nb_nodes, TB>>>(W_self1, W_neigh1, b1);
    k_edge2<<<nb_edges, TB>>>(src, dst);
    k_node2<<<nb_nodes, TB>>>(W_self2, W_neigh2, b2, out);
}

// round 2
// speedup vs baseline: 1.4451x; 1.4451x over previous
#include <cuda_runtime.h>
#include <cuda_fp16.h>

#define N_NODES 100000
#define N_EDGES 6400000
#define F_IN 5
#define F_HID 5
#define F_OUT 10

// Scratch (__device__ globals — allocation-free rule).
// g_xpad/g_h: f32 rows padded to 32B (one aligned L2 sector per gather).
// g_agg1/g_agg2: 16B rows of 8 f16 lanes, written by ONE red.v4.f16x2 per edge.
__device__ __align__(32) float g_xpad[N_NODES][8];
__device__ __align__(32) float g_h[N_NODES][8];
__device__ __align__(16) uint4 g_agg1[N_NODES];  // lanes: x0..x4, deg, pad, pad (f16)
__device__ __align__(16) uint4 g_agg2[N_NODES];  // lanes: (h0..h4)-0.5, pad x3 (f16)

__device__ __forceinline__ void red_add_v4_f16x2(uint4* p, unsigned r0, unsigned r1,
                                                 unsigned r2, unsigned r3) {
    unsigned long long gp = __cvta_generic_to_global((void*)p);
    asm volatile("red.global.add.noftz.v4.f16x2 [%0], {%1,%2,%3,%4};"
                 :: "l"(gp), "r"(r0), "r"(r1), "r"(r2), "r"(r3) : "memory");
}

__device__ __forceinline__ float sigmoidf(float z) {
    return 1.0f / (1.0f + __expf(-z));
}

__device__ __forceinline__ unsigned pack2(float a, float b) {
    __half2 h = __floats2half2_rn(a, b);
    return *(unsigned*)&h;
}

// ---------------------------------------------------------------------------
// K0: pad x into g_xpad and zero both f16 aggregation buffers.
__global__ void k_init(const float* __restrict__ x) {
    int i = blockIdx.x * blockDim.x + threadIdx.x;
    if (i >= N_NODES) return;
    const float* xr = x + i * F_IN;
    *(float4*)&g_xpad[i][0] = make_float4(xr[0], xr[1], xr[2], xr[3]);
    *(float4*)&g_xpad[i][4] = make_float4(xr[4], 0.f, 0.f, 0.f);
    uint4 z = make_uint4(0u, 0u, 0u, 0u);
    g_agg1[i] = z;
    g_agg2[i] = z;
}

// ---------------------------------------------------------------------------
// K1: layer-1 edge scatter — ONE 16B vector red per edge.
// Lanes: {x0,x1},{x2,x3},{x4,1.0(deg)},{0,0}
__global__ void k_edge1(const int* __restrict__ src, const int* __restrict__ dst) {
    int e = blockIdx.x * blockDim.x + threadIdx.x;
    if (e >= N_EDGES) return;
    int s = src[e];
    int d = dst[e];
    float4 a  = *(const float4*)&g_xpad[s][0];
    float  a4 = g_xpad[s][4];
    red_add_v4_f16x2(&g_agg1[d],
                     pack2(a.x, a.y), pack2(a.z, a.w),
                     pack2(a4, 1.0f), 0u);
}

// ---------------------------------------------------------------------------
// K2: layer-1 node update: h = sigmoid(x@Ws1 + (agg/deg)@Wn1 + b1)
__global__ void k_node1(const float* __restrict__ Ws, const float* __restrict__ Wn,
                        const float* __restrict__ b) {
    int i = blockIdx.x * blockDim.x + threadIdx.x;
    if (i >= N_NODES) return;
    float4 xa = *(const float4*)&g_xpad[i][0];
    float  x4 = g_xpad[i][4];
    uint4 au = g_agg1[i];
    float2 p0 = __half22float2(*(__half2*)&au.x);
    float2 p1 = __half22float2(*(__half2*)&au.y);
    float2 p2 = __half22float2(*(__half2*)&au.z);
    float deg = p2.y;
    float inv = 1.0f / fmaxf(deg, 1.0f);
    float xv[5] = {xa.x, xa.y, xa.z, xa.w, x4};
    float hn[5] = {p0.x * inv, p0.y * inv, p1.x * inv, p1.y * inv, p2.x * inv};
    float o[F_HID];
#pragma unroll
    for (int j = 0; j < F_HID; j++) o[j] = b[j];
#pragma unroll
    for (int k = 0; k < F_IN; k++) {
        float xk = xv[k], hk = hn[k];
#pragma unroll
        for (int j = 0; j < F_HID; j++)
            o[j] += xk * __ldg(&Ws[k * F_HID + j]) + hk * __ldg(&Wn[k * F_HID + j]);
    }
#pragma unroll
    for (int j = 0; j < F_HID; j++) o[j] = sigmoidf(o[j]);
    // store h (f32) and deg (reused by layer 2) in the padded row
    *(float4*)&g_h[i][0] = make_float4(o[0], o[1], o[2], o[3]);
    *(float4*)&g_h[i][4] = make_float4(o[4], deg, 0.f, 0.f);
}

// ---------------------------------------------------------------------------
// K3: layer-2 edge scatter — ONE 16B vector red per edge.
// Accumulate (h - 0.5) so f16 partial sums random-walk instead of growing
// linearly (precision). Lanes: {h0-.5,h1-.5},{h2-.5,h3-.5},{h4-.5,0},{0,0}
__global__ void k_edge2(const int* __restrict__ src, const int* __restrict__ dst) {
    int e = blockIdx.x * blockDim.x + threadIdx.x;
    if (e >= N_EDGES) return;
    int s = src[e];
    int d = dst[e];
    float4 a  = *(const float4*)&g_h[s][0];
    float  a4 = g_h[s][4];
    red_add_v4_f16x2(&g_agg2[d],
                     pack2(a.x - 0.5f, a.y - 0.5f),
                     pack2(a.z - 0.5f, a.w - 0.5f),
                     pack2(a4 - 0.5f, 0.f), 0u);
}

// ---------------------------------------------------------------------------
// K4: layer-2 node update -> out = sigmoid(h@Ws2 + (agg2/deg)@Wn2 + b2)
// agg2 holds sum(h - 0.5); true sum = agg2 + 0.5*deg (deg exact).
__global__ void k_node2(const float* __restrict__ Ws, const float* __restrict__ Wn,
                        const float* __restrict__ b, float* __restrict__ out) {
    int i = blockIdx.x * blockDim.x + threadIdx.x;
    if (i >= N_NODES) return;
    float4 ha = *(const float4*)&g_h[i][0];
    float4 hb = *(const float4*)&g_h[i][4];   // .x = h4, .y = deg
    float  h4 = hb.x;
    float  deg = hb.y;
    uint4 au = g_agg2[i];
    float2 p0 = __half22float2(*(__half2*)&au.x);
    float2 p1 = __half22float2(*(__half2*)&au.y);
    float2 p2 = __half22float2(*(__half2*)&au.z);
    float half_deg = 0.5f * deg;
    float inv = 1.0f / fmaxf(deg, 1.0f);
    float hv[5] = {ha.x, ha.y, ha.z, ha.w, h4};
    float hn[5] = {(p0.x + half_deg) * inv, (p0.y + half_deg) * inv,
                   (p1.x + half_deg) * inv, (p1.y + half_deg) * inv,
                   (p2.x + half_deg) * inv};
    float o[F_OUT];
#pragma unroll
    for (int j = 0; j < F_OUT; j++) o[j] = b[j];
#pragma unroll
    for (int k = 0; k < F_HID; k++) {
        float hk = hv[k], nk = hn[k];
#pragma unroll
        for (int j = 0; j < F_OUT; j++)
            o[j] += hk * __ldg(&Ws[k * F_OUT + j]) + nk * __ldg(&Wn[k * F_OUT + j]);
    }
    float* orow = out + i * F_OUT;
#pragma unroll
    for (int j = 0; j < F_OUT; j++) orow[j] = sigmoidf(o[j]);
}

// ---------------------------------------------------------------------------
extern "C" void kernel_launch(void* const* d_in, const int* in_sizes, int n_in,
                              void* d_out, int out_size) {
    const float* x       = (const float*)d_in[0];
    const int*   src     = (const int*)d_in[1];
    const int*   dst     = (const int*)d_in[2];
    const float* W_self1 = (const float*)d_in[3];
    const float* W_neigh1= (const float*)d_in[4];
    const float* b1      = (const float*)d_in[5];
    const float* W_self2 = (const float*)d_in[6];
    const float* W_neigh2= (const float*)d_in[7];
    const float* b2      = (const float*)d_in[8];
    float* out = (float*)d_out;

    const int TB = 256;
    int nb_nodes = (N_NODES + TB - 1) / TB;
    int nb_edges = (N_EDGES + TB - 1) / TB;

    k_init<<<nb_nodes, TB>>>(x);
    k_edge1<<<nb_edges, TB>>>(src, dst);
    k_node1<<<nb_nodes, TB>>>(W_self1, W_neigh1, b1);
    k_edge2<<<nb_edges, TB>>>(src, dst);
    k_node2<<<nb_nodes, TB>>>(W_self2, W_neigh2, b2, out);
}

// round 3
// speedup vs baseline: 1.4740x; 1.0200x over previous
#include <cuda_runtime.h>
#include <cuda_fp16.h>

#define N_NODES 100000
#define N_EDGES 6400000
#define F_IN 5
#define F_HID 5
#define F_OUT 10

// __device__ scratch (allocation-free rule).
// g_x16 / g_h16: f16x8 node rows (16B) pre-packed in red-message layout.
// g_h: f32 row {h0..h4, deg, 0, 0} for exact self-term in layer 2.
__device__ __align__(16) uint4 g_x16[N_NODES];   // {x0,x1},{x2,x3},{x4,1.0},{0,0}
__device__ __align__(16) uint4 g_h16[N_NODES];   // {h0-.5,h1-.5},{h2-.5,h3-.5},{h4-.5,0},{0,0}
__device__ __align__(32) float g_h[N_NODES][8];
__device__ __align__(16) uint4 g_agg1[N_NODES];  // f16 lanes: x-sums, deg
__device__ __align__(16) uint4 g_agg2[N_NODES];  // f16 lanes: (h-.5)-sums

__device__ __forceinline__ void red_add_v4_f16x2(uint4* p, uint4 v) {
    unsigned long long gp = __cvta_generic_to_global((void*)p);
    asm volatile("red.global.add.noftz.v4.f16x2 [%0], {%1,%2,%3,%4};"
                 :: "l"(gp), "r"(v.x), "r"(v.y), "r"(v.z), "r"(v.w) : "memory");
}

__device__ __forceinline__ uint4 ldg_u4(const uint4* p) {
    uint4 v;
    asm volatile("ld.global.nc.v4.u32 {%0,%1,%2,%3}, [%4];"
                 : "=r"(v.x), "=r"(v.y), "=r"(v.z), "=r"(v.w)
                 : "l"(__cvta_generic_to_global((const void*)p)));
    return v;
}

__device__ __forceinline__ float sigmoidf(float z) {
    return 1.0f / (1.0f + __expf(-z));
}

__device__ __forceinline__ unsigned pack2(float a, float b) {
    __half2 h = __floats2half2_rn(a, b);
    return *(unsigned*)&h;
}

// ---------------------------------------------------------------------------
// K0: pack x into f16 red-layout rows; zero aggregation buffers.
__global__ void k_init(const float* __restrict__ x) {
    int i = blockIdx.x * blockDim.x + threadIdx.x;
    if (i >= N_NODES) return;
    const float* xr = x + i * F_IN;
    float v0 = __ldg(xr), v1 = __ldg(xr + 1), v2 = __ldg(xr + 2),
          v3 = __ldg(xr + 3), v4 = __ldg(xr + 4);
    g_x16[i] = make_uint4(pack2(v0, v1), pack2(v2, v3), pack2(v4, 1.0f), 0u);
    uint4 z = make_uint4(0u, 0u, 0u, 0u);
    g_agg1[i] = z;
    g_agg2[i] = z;
}

// ---------------------------------------------------------------------------
// Edge scatter, coarsened x4: int4 index loads, 4 independent 16B gathers
// (MLP=4), then 4 vector reds. Raw gathered row IS the red message.
template <int LAYER>
__global__ void k_edge(const int4* __restrict__ src4, const int4* __restrict__ dst4) {
    int t = blockIdx.x * blockDim.x + threadIdx.x;
    if (t >= N_EDGES / 4) return;
    int4 s = __ldg(&src4[t]);
    int4 d = __ldg(&dst4[t]);
    const uint4* tab = (LAYER == 1) ? g_x16 : g_h16;
    uint4* agg = (LAYER == 1) ? g_agg1 : g_agg2;
    uint4 r0 = ldg_u4(&tab[s.x]);
    uint4 r1 = ldg_u4(&tab[s.y]);
    uint4 r2 = ldg_u4(&tab[s.z]);
    uint4 r3 = ldg_u4(&tab[s.w]);
    red_add_v4_f16x2(&agg[d.x], r0);
    red_add_v4_f16x2(&agg[d.y], r1);
    red_add_v4_f16x2(&agg[d.z], r2);
    red_add_v4_f16x2(&agg[d.w], r3);
}

// ---------------------------------------------------------------------------
// K2: layer-1 node update: h = sigmoid(x@Ws1 + (agg1/deg)@Wn1 + b1)
// Self-term uses exact f32 x from the input tensor.
__global__ void k_node1(const float* __restrict__ x,
                        const float* __restrict__ Ws, const float* __restrict__ Wn,
                        const float* __restrict__ b) {
    int i = blockIdx.x * blockDim.x + threadIdx.x;
    if (i >= N_NODES) return;
    const float* xr = x + i * F_IN;
    float xv[5] = {__ldg(xr), __ldg(xr + 1), __ldg(xr + 2), __ldg(xr + 3), __ldg(xr + 4)};
    uint4 au = g_agg1[i];
    float2 p0 = __half22float2(*(__half2*)&au.x);
    float2 p1 = __half22float2(*(__half2*)&au.y);
    float2 p2 = __half22float2(*(__half2*)&au.z);
    float deg = p2.y;
    float inv = 1.0f / fmaxf(deg, 1.0f);
    float hn[5] = {p0.x * inv, p0.y * inv, p1.x * inv, p1.y * inv, p2.x * inv};
    float o[F_HID];
#pragma unroll
    for (int j = 0; j < F_HID; j++) o[j] = b[j];
#pragma unroll
    for (int k = 0; k < F_IN; k++) {
        float xk = xv[k], hk = hn[k];
#pragma unroll
        for (int j = 0; j < F_HID; j++)
            o[j] += xk * __ldg(&Ws[k * F_HID + j]) + hk * __ldg(&Wn[k * F_HID + j]);
    }
#pragma unroll
    for (int j = 0; j < F_HID; j++) o[j] = sigmoidf(o[j]);
    // exact f32 row for the layer-2 self-term (+ deg), and f16 red-layout row
    *(float4*)&g_h[i][0] = make_float4(o[0], o[1], o[2], o[3]);
    *(float4*)&g_h[i][4] = make_float4(o[4], deg, 0.f, 0.f);
    g_h16[i] = make_uint4(pack2(o[0] - 0.5f, o[1] - 0.5f),
                          pack2(o[2] - 0.5f, o[3] - 0.5f),
                          pack2(o[4] - 0.5f, 0.f), 0u);
}

// ---------------------------------------------------------------------------
// K4: layer-2 node update -> out = sigmoid(h@Ws2 + (agg2/deg)@Wn2 + b2)
// agg2 holds sum(h - 0.5); true sum = agg2 + 0.5*deg.
__global__ void k_node2(const float* __restrict__ Ws, const float* __restrict__ Wn,
                        const float* __restrict__ b, float* __restrict__ out) {
    int i = blockIdx.x * blockDim.x + threadIdx.x;
    if (i >= N_NODES) return;
    float4 ha = *(const float4*)&g_h[i][0];
    float4 hb = *(const float4*)&g_h[i][4];   // .x = h4, .y = deg
    float deg = hb.y;
    uint4 au = g_agg2[i];
    float2 p0 = __half22float2(*(__half2*)&au.x);
    float2 p1 = __half22float2(*(__half2*)&au.y);
    float2 p2 = __half22float2(*(__half2*)&au.z);
    float half_deg = 0.5f * deg;
    float inv = 1.0f / fmaxf(deg, 1.0f);
    float hv[5] = {ha.x, ha.y, ha.z, ha.w, hb.x};
    float hn[5] = {(p0.x + half_deg) * inv, (p0.y + half_deg) * inv,
                   (p1.x + half_deg) * inv, (p1.y + half_deg) * inv,
                   (p2.x + half_deg) * inv};
    float o[F_OUT];
#pragma unroll
    for (int j = 0; j < F_OUT; j++) o[j] = b[j];
#pragma unroll
    for (int k = 0; k < F_HID; k++) {
        float hk = hv[k], nk = hn[k];
#pragma unroll
        for (int j = 0; j < F_OUT; j++)
            o[j] += hk * __ldg(&Ws[k * F_OUT + j]) + nk * __ldg(&Wn[k * F_OUT + j]);
    }
    float* orow = out + i * F_OUT;
#pragma unroll
    for (int j = 0; j < F_OUT; j++) orow[j] = sigmoidf(o[j]);
}

// ---------------------------------------------------------------------------
extern "C" void kernel_launch(void* const* d_in, const int* in_sizes, int n_in,
                              void* d_out, int out_size) {
    const float* x       = (const float*)d_in[0];
    const int*   src     = (const int*)d_in[1];
    const int*   dst     = (const int*)d_in[2];
    const float* W_self1 = (const float*)d_in[3];
    const float* W_neigh1= (const float*)d_in[4];
    const float* b1      = (const float*)d_in[5];
    const float* W_self2 = (const float*)d_in[6];
    const float* W_neigh2= (const float*)d_in[7];
    const float* b2      = (const float*)d_in[8];
    float* out = (float*)d_out;

    const int TB = 256;
    int nb_nodes = (N_NODES + TB - 1) / TB;
    int nb_edge4 = (N_EDGES / 4 + TB - 1) / TB;

    k_init<<<nb_nodes, TB>>>(x);
    k_edge<1><<<nb_edge4, TB>>>((const int4*)src, (const int4*)dst);
    k_node1<<<nb_nodes, TB>>>(x, W_self1, W_neigh1, b1);
    k_edge<2><<<nb_edge4, TB>>>((const int4*)src, (const int4*)dst);
    k_node2<<<nb_nodes, TB>>>(W_self2, W_neigh2, b2, out);
}